// round 11
// baseline (speedup 1.0000x reference)
#include <cuda_runtime.h>
#include <cstdint>

#define BATCH 32
#define NN    784
#define DD    512
#define RESO  28
#define KK    10
#define BT    112
#define NTB   7
#define NPAIR 28          // triangular tile pairs (p<=q)
#define NTHR  224         // 16 x 14 threads
#define KC    16          // k-chunk depth
#define SA_ST 20          // floats per i-row of A chunk (16 + 4 pad)
#define SB_ST 120         // floats per k-row of B chunk (112 + 8 pad)
#define ST_ST 116         // transpose-tile stride (floats)
#define INF_VAL 100000.0f

typedef unsigned long long ull;

__device__ __align__(256) float g_xn[(size_t)BATCH * NN * DD];
__device__ __align__(256) float g_sq[BATCH * NN];
__device__ __align__(256) float g_dist[(size_t)BATCH * NN * NN];

__device__ __forceinline__ ull fma2(ull a, ull b, ull c) {
    ull d; asm("fma.rn.f32x2 %0,%1,%2,%3;" : "=l"(d) : "l"(a), "l"(b), "l"(c)); return d;
}
__device__ __forceinline__ ull dup2(float x) {
    ull d; asm("mov.b64 %0,{%1,%1};" : "=l"(d) : "f"(x)); return d;
}
__device__ __forceinline__ float lo2(ull v) { return __uint_as_float((unsigned)v); }
__device__ __forceinline__ float hi2(ull v) { return __uint_as_float((unsigned)(v >> 32)); }

// ---------- Kernel 1: exact-rounding normalize (warp per vector) ----------
__global__ void norm_kernel(const float* __restrict__ in) {
    const int vec  = blockIdx.x * 8 + (threadIdx.x >> 5);
    const int lane = threadIdx.x & 31;
    const float4* v = reinterpret_cast<const float4*>(in + (size_t)vec * DD);
    float4 a0 = v[lane], a1 = v[lane + 32], a2 = v[lane + 64], a3 = v[lane + 96];

    float s = 0.0f;
    s = fmaf(a0.x,a0.x,s); s = fmaf(a0.y,a0.y,s); s = fmaf(a0.z,a0.z,s); s = fmaf(a0.w,a0.w,s);
    s = fmaf(a1.x,a1.x,s); s = fmaf(a1.y,a1.y,s); s = fmaf(a1.z,a1.z,s); s = fmaf(a1.w,a1.w,s);
    s = fmaf(a2.x,a2.x,s); s = fmaf(a2.y,a2.y,s); s = fmaf(a2.z,a2.z,s); s = fmaf(a2.w,a2.w,s);
    s = fmaf(a3.x,a3.x,s); s = fmaf(a3.y,a3.y,s); s = fmaf(a3.z,a3.z,s); s = fmaf(a3.w,a3.w,s);
    #pragma unroll
    for (int off = 16; off > 0; off >>= 1)
        s = __fadd_rn(s, __shfl_xor_sync(0xffffffffu, s, off));

    const float nrm = fmaxf(__fsqrt_rn(s), 1e-12f);
    a0.x=__fdiv_rn(a0.x,nrm); a0.y=__fdiv_rn(a0.y,nrm); a0.z=__fdiv_rn(a0.z,nrm); a0.w=__fdiv_rn(a0.w,nrm);
    a1.x=__fdiv_rn(a1.x,nrm); a1.y=__fdiv_rn(a1.y,nrm); a1.z=__fdiv_rn(a1.z,nrm); a1.w=__fdiv_rn(a1.w,nrm);
    a2.x=__fdiv_rn(a2.x,nrm); a2.y=__fdiv_rn(a2.y,nrm); a2.z=__fdiv_rn(a2.z,nrm); a2.w=__fdiv_rn(a2.w,nrm);
    a3.x=__fdiv_rn(a3.x,nrm); a3.y=__fdiv_rn(a3.y,nrm); a3.z=__fdiv_rn(a3.z,nrm); a3.w=__fdiv_rn(a3.w,nrm);

    float s2 = 0.0f;
    s2 = fmaf(a0.x,a0.x,s2); s2 = fmaf(a0.y,a0.y,s2); s2 = fmaf(a0.z,a0.z,s2); s2 = fmaf(a0.w,a0.w,s2);
    s2 = fmaf(a1.x,a1.x,s2); s2 = fmaf(a1.y,a1.y,s2); s2 = fmaf(a1.z,a1.z,s2); s2 = fmaf(a1.w,a1.w,s2);
    s2 = fmaf(a2.x,a2.x,s2); s2 = fmaf(a2.y,a2.y,s2); s2 = fmaf(a2.z,a2.z,s2); s2 = fmaf(a2.w,a2.w,s2);
    s2 = fmaf(a3.x,a3.x,s2); s2 = fmaf(a3.y,a3.y,s2); s2 = fmaf(a3.z,a3.z,s2); s2 = fmaf(a3.w,a3.w,s2);
    #pragma unroll
    for (int off = 16; off > 0; off >>= 1)
        s2 = __fadd_rn(s2, __shfl_xor_sync(0xffffffffu, s2, off));

    float4* o = reinterpret_cast<float4*>(g_xn + (size_t)vec * DD);
    o[lane] = a0; o[lane + 32] = a1; o[lane + 64] = a2; o[lane + 96] = a3;
    if (lane == 0) g_sq[vec] = s2;
}

// ---------- Kernel 2: symmetric tiled GEMM -> dist (+rel+mask) into g_dist ----------
// A tile i-major (LDS.128 per 4 k's per row), B tile k-major floats (natural
// f32x2 column pairing). 112x112 tile, 224 threads, 7x8 outputs per thread.
__global__ void __launch_bounds__(NTHR, 2)
MediumRangeEdge_11072425689094_kernel(const float* __restrict__ rel) {
    extern __shared__ char smraw[];
    float* sA0 = (float*)smraw;                    // [112][SA_ST] = 8960 B
    float* sA1 = (float*)(smraw + 8960);
    float* sB0 = (float*)(smraw + 17920);          // [16][SB_ST]  = 7680 B
    float* sB1 = (float*)(smraw + 25600);
    float* sT  = (float*)smraw;                    // transpose tile (aliases, used after)

    const int b = blockIdx.x / NPAIR;
    int rem = blockIdx.x - b * NPAIR;
    int p = 0, cnt = NTB;
    while (rem >= cnt) { rem -= cnt; --cnt; ++p; }
    const int q = p + rem;
    const int pbase = p * BT, qbase = q * BT;

    const int tid = threadIdx.x;
    const int tx  = tid & 15;
    const int ty  = tid >> 4;

    const int r0 = tid >> 2,          kq0 = tid & 3;
    const int r1 = (tid + NTHR) >> 2, kq1 = (tid + NTHR) & 3;

    const float4* gA = (const float4*)(g_xn + ((size_t)b * NN + pbase) * DD);
    const float4* gB = (const float4*)(g_xn + ((size_t)b * NN + qbase) * DD);

    float4 fa0 = gA[r0 * (DD/4) + kq0], fa1 = gA[r1 * (DD/4) + kq1];
    float4 fb0 = gB[r0 * (DD/4) + kq0], fb1 = gB[r1 * (DD/4) + kq1];

    ull acc[7][4];
    #pragma unroll
    for (int s = 0; s < 7; ++s)
        #pragma unroll
        for (int c = 0; c < 4; ++c) acc[s][c] = 0ULL;

    for (int kc = 0; kc < DD / KC; ++kc) {
        float* A = (kc & 1) ? sA1 : sA0;
        float* B = (kc & 1) ? sB1 : sB0;

        // STS A: i-major, direct float4
        *(float4*)(A + r0 * SA_ST + 4 * kq0) = fa0;
        *(float4*)(A + r1 * SA_ST + 4 * kq1) = fa1;
        // STS B: k-major scatter (conflict-free: (r + 24k) mod 32 distinct per warp)
        B[(4*kq0+0)*SB_ST + r0] = fb0.x;
        B[(4*kq0+1)*SB_ST + r0] = fb0.y;
        B[(4*kq0+2)*SB_ST + r0] = fb0.z;
        B[(4*kq0+3)*SB_ST + r0] = fb0.w;
        B[(4*kq1+0)*SB_ST + r1] = fb1.x;
        B[(4*kq1+1)*SB_ST + r1] = fb1.y;
        B[(4*kq1+2)*SB_ST + r1] = fb1.z;
        B[(4*kq1+3)*SB_ST + r1] = fb1.w;
        __syncthreads();

        if (kc + 1 < DD / KC) {  // prefetch next chunk
            const int ko = (kc + 1) * (KC / 4);
            fa0 = gA[r0*(DD/4) + ko + kq0]; fa1 = gA[r1*(DD/4) + ko + kq1];
            fb0 = gB[r0*(DD/4) + ko + kq0]; fb1 = gB[r1*(DD/4) + ko + kq1];
        }

        #pragma unroll
        for (int k4 = 0; k4 < KC / 4; ++k4) {
            float4 aa[7];
            #pragma unroll
            for (int s = 0; s < 7; ++s)
                aa[s] = *(const float4*)(A + (tx + 16*s) * SA_ST + 4 * k4);
            #pragma unroll
            for (int kk = 0; kk < 4; ++kk) {
                const float* Brow = B + (4*k4 + kk) * SB_ST + 8 * ty;
                const ulonglong2 bb0 = *(const ulonglong2*)(Brow);
                const ulonglong2 bb1 = *(const ulonglong2*)(Brow + 4);
                #pragma unroll
                for (int s = 0; s < 7; ++s) {
                    const float af = (kk == 0) ? aa[s].x : (kk == 1) ? aa[s].y
                                   : (kk == 2) ? aa[s].z : aa[s].w;
                    const ull av = dup2(af);
                    acc[s][0] = fma2(av, bb0.x, acc[s][0]);
                    acc[s][1] = fma2(av, bb0.y, acc[s][1]);
                    acc[s][2] = fma2(av, bb1.x, acc[s][2]);
                    acc[s][3] = fma2(av, bb1.y, acc[s][3]);
                }
            }
        }
        __syncthreads();
    }

    // ---- epilogue: dist = ((sq_i + sq_j) - 2*dot) + rel (+INF mask) ----
    float sqj[8]; int jr[8], jc[8];
    #pragma unroll
    for (int cc = 0; cc < 8; ++cc) {
        const int j = qbase + 8*ty + cc;
        sqj[cc] = g_sq[b*NN + j];
        jr[cc] = j / RESO; jc[cc] = j - jr[cc]*RESO;
    }
    #pragma unroll
    for (int s = 0; s < 7; ++s) {
        const int i  = pbase + tx + 16*s;
        const float sqi = g_sq[b*NN + i];
        const int ri = i / RESO, ci = i - ri*RESO;
        const float4 rl0 = *(const float4*)(rel + (size_t)i*NN + qbase + 8*ty);
        const float4 rl1 = *(const float4*)(rel + (size_t)i*NN + qbase + 8*ty + 4);
        const float rv[8] = {rl0.x, rl0.y, rl0.z, rl0.w, rl1.x, rl1.y, rl1.z, rl1.w};
        float ov[8];
        #pragma unroll
        for (int c = 0; c < 4; ++c) {
            const float d0 = lo2(acc[s][c]), d1 = hi2(acc[s][c]);
            float v0 = __fadd_rn(__fsub_rn(__fadd_rn(sqi, sqj[2*c]),
                                           __fmul_rn(2.0f, d0)), rv[2*c]);
            float v1 = __fadd_rn(__fsub_rn(__fadd_rn(sqi, sqj[2*c+1]),
                                           __fmul_rn(2.0f, d1)), rv[2*c+1]);
            int dr = ri - jr[2*c],   dc = ci - jc[2*c];
            if (dr >= -1 && dr <= 1 && dc >= -1 && dc <= 1) v0 = __fadd_rn(v0, INF_VAL);
            dr = ri - jr[2*c+1]; dc = ci - jc[2*c+1];
            if (dr >= -1 && dr <= 1 && dc >= -1 && dc <= 1) v1 = __fadd_rn(v1, INF_VAL);
            ov[2*c] = v0; ov[2*c+1] = v1;
        }
        float4* dst = (float4*)(g_dist + ((size_t)b*NN + i)*NN + qbase + 8*ty);
        dst[0] = make_float4(ov[0], ov[1], ov[2], ov[3]);
        dst[1] = make_float4(ov[4], ov[5], ov[6], ov[7]);
        if (p != q) {
            #pragma unroll
            for (int cc = 0; cc < 8; ++cc)
                sT[(8*ty + cc)*ST_ST + tx + 16*s] = ov[cc];
        }
    }

    if (p != q) {   // symmetric write: dist[j][i] (formula symmetric, rounding identical)
        __syncthreads();
        const int jl = tid >> 1, hf = tid & 1;
        const float*  srow = sT + jl*ST_ST + hf*56;
        float* drow = g_dist + ((size_t)b*NN + qbase + jl)*NN + pbase + hf*56;
        #pragma unroll
        for (int m = 0; m < 14; ++m)
            ((float4*)drow)[m] = ((const float4*)srow)[m];
    }
}

// ---------- Kernel 3: top-K per row (warp per row), float4 + prefilter ----------
__global__ void __launch_bounds__(1024)
topk_kernel(float* __restrict__ out) {
    const int row  = blockIdx.x * 32 + (threadIdx.x >> 5);
    const int lane = threadIdx.x & 31;
    const float4* drow4 = (const float4*)(g_dist + (size_t)row * NN);

    ull list[KK];
    #pragma unroll
    for (int qq = 0; qq < KK; ++qq) list[qq] = ~0ULL;

    #pragma unroll 1
    for (int t = 0; t < 6; ++t) {
        const int f4 = lane + 32 * t;
        const float4 v = __ldg(drow4 + f4);
        const unsigned thr = (unsigned)(list[KK-1] >> 32);
        const float vv[4] = {v.x, v.y, v.z, v.w};
        #pragma unroll
        for (int e = 0; e < 4; ++e) {
            unsigned u = __float_as_uint(vv[e]);
            u = (u & 0x80000000u) ? ~u : (u | 0x80000000u);
            if (u <= thr) {
                const ull key = ((ull)u << 32) | (unsigned)(4*f4 + e);
                if (key < list[KK-1]) {
                    list[KK-1] = key;
                    #pragma unroll
                    for (int qq = KK-1; qq > 0; --qq)
                        if (list[qq] < list[qq-1]) {
                            const ull tk = list[qq-1]; list[qq-1] = list[qq]; list[qq] = tk;
                        }
                }
            }
        }
    }
    if (lane < 4) {   // remainder: float4 indices 192..195 (j = 768..783)
        const int f4 = 192 + lane;
        const float4 v = __ldg(drow4 + f4);
        const float vv[4] = {v.x, v.y, v.z, v.w};
        #pragma unroll
        for (int e = 0; e < 4; ++e) {
            unsigned u = __float_as_uint(vv[e]);
            u = (u & 0x80000000u) ? ~u : (u | 0x80000000u);
            const ull key = ((ull)u << 32) | (unsigned)(4*f4 + e);
            if (key < list[KK-1]) {
                list[KK-1] = key;
                #pragma unroll
                for (int qq = KK-1; qq > 0; --qq)
                    if (list[qq] < list[qq-1]) {
                        const ull tk = list[qq-1]; list[qq-1] = list[qq]; list[qq] = tk;
                    }
            }
        }
    }

    const int bofs = (row / NN) * NN;
    const int base = row * (KK * 3);
    #pragma unroll
    for (int k = 0; k < KK; ++k) {
        ull v = list[0];
        #pragma unroll
        for (int off = 16; off > 0; off >>= 1) {
            const ull o = __shfl_xor_sync(0xffffffffu, v, off);
            if (o < v) v = o;
        }
        if (lane == k) {
            out[base + 3*k + 0] = (float)((int)(v & 0xffffffffULL) + bofs);  // dst
            out[base + 3*k + 1] = (float)row;                                // src
            out[base + 3*k + 2] = 0.0f;                                      // relation
        }
        if (list[0] == v) {
            #pragma unroll
            for (int qq = 0; qq < KK-1; ++qq) list[qq] = list[qq+1];
            list[KK-1] = ~0ULL;
        }
    }
}

extern "C" void kernel_launch(void* const* d_in, const int* in_sizes, int n_in,
                              void* d_out, int out_size) {
    (void)out_size;
    const float* node_feature = (const float*)d_in[0];
    const float* relative_pos = (const float*)d_in[1];
    if (n_in >= 2 && in_sizes[0] < in_sizes[1]) {
        node_feature = (const float*)d_in[1];
        relative_pos = (const float*)d_in[0];
    }
    float* out = (float*)d_out;

    const int smem = BT * ST_ST * (int)sizeof(float);   // 51968 B (covers staging too)
    static int attr_done = 0;
    if (!attr_done) {
        cudaFuncSetAttribute(MediumRangeEdge_11072425689094_kernel,
                             cudaFuncAttributeMaxDynamicSharedMemorySize, smem);
        attr_done = 1;
    }

    norm_kernel<<<(BATCH * NN) / 8, 256>>>(node_feature);
    MediumRangeEdge_11072425689094_kernel<<<BATCH * NPAIR, NTHR, smem>>>(relative_pos);
    topk_kernel<<<(BATCH * NN) / 32, 1024>>>(out);
}

// round 12
// speedup vs baseline: 1.1058x; 1.1058x over previous
#include <cuda_runtime.h>
#include <cstdint>

#define BATCH 32
#define NN    784
#define DD    512
#define RESO  28
#define KK    10
#define BT    112
#define NTB   7
#define NPAIR 28          // triangular tile pairs (p<=q)
#define NTHR  224         // 16 x 14 threads
#define KC    16          // k-chunk depth
#define SA_ST 116         // floats per k-row of A (112+4 pad)
#define SB_ST 58          // u64 per k-row of B (56+2 pad)
#define SD_ST 113         // dist-tile stride (floats, odd => conflict-free both ways)
#define INF_VAL 100000.0f

typedef unsigned long long ull;

__device__ __align__(256) float g_xn[(size_t)BATCH * NN * DD];
__device__ __align__(256) float g_sq[BATCH * NN];
__device__ __align__(256) ull   g_part[(size_t)BATCH * NN * NTB * KK];   // 14 MB

__device__ __forceinline__ ull fma2(ull a, ull b, ull c) {
    ull d; asm("fma.rn.f32x2 %0,%1,%2,%3;" : "=l"(d) : "l"(a), "l"(b), "l"(c)); return d;
}
__device__ __forceinline__ ull dup2(float x) {
    ull d; asm("mov.b64 %0,{%1,%1};" : "=l"(d) : "f"(x)); return d;
}
__device__ __forceinline__ float lo2(ull v) { return __uint_as_float((unsigned)v); }
__device__ __forceinline__ float hi2(ull v) { return __uint_as_float((unsigned)(v >> 32)); }
__device__ __forceinline__ unsigned fmap(float v) {
    unsigned u = __float_as_uint(v);
    return (u & 0x80000000u) ? ~u : (u | 0x80000000u);   // order-preserving map
}

// ---------- Kernel 1: exact-rounding normalize (warp per vector) ----------
__global__ void norm_kernel(const float* __restrict__ in) {
    const int vec  = blockIdx.x * 8 + (threadIdx.x >> 5);
    const int lane = threadIdx.x & 31;
    const float4* v = reinterpret_cast<const float4*>(in + (size_t)vec * DD);
    float4 a0 = v[lane], a1 = v[lane + 32], a2 = v[lane + 64], a3 = v[lane + 96];

    float s = 0.0f;
    s = fmaf(a0.x,a0.x,s); s = fmaf(a0.y,a0.y,s); s = fmaf(a0.z,a0.z,s); s = fmaf(a0.w,a0.w,s);
    s = fmaf(a1.x,a1.x,s); s = fmaf(a1.y,a1.y,s); s = fmaf(a1.z,a1.z,s); s = fmaf(a1.w,a1.w,s);
    s = fmaf(a2.x,a2.x,s); s = fmaf(a2.y,a2.y,s); s = fmaf(a2.z,a2.z,s); s = fmaf(a2.w,a2.w,s);
    s = fmaf(a3.x,a3.x,s); s = fmaf(a3.y,a3.y,s); s = fmaf(a3.z,a3.z,s); s = fmaf(a3.w,a3.w,s);
    #pragma unroll
    for (int off = 16; off > 0; off >>= 1)
        s = __fadd_rn(s, __shfl_xor_sync(0xffffffffu, s, off));

    const float nrm = fmaxf(__fsqrt_rn(s), 1e-12f);
    a0.x=__fdiv_rn(a0.x,nrm); a0.y=__fdiv_rn(a0.y,nrm); a0.z=__fdiv_rn(a0.z,nrm); a0.w=__fdiv_rn(a0.w,nrm);
    a1.x=__fdiv_rn(a1.x,nrm); a1.y=__fdiv_rn(a1.y,nrm); a1.z=__fdiv_rn(a1.z,nrm); a1.w=__fdiv_rn(a1.w,nrm);
    a2.x=__fdiv_rn(a2.x,nrm); a2.y=__fdiv_rn(a2.y,nrm); a2.z=__fdiv_rn(a2.z,nrm); a2.w=__fdiv_rn(a2.w,nrm);
    a3.x=__fdiv_rn(a3.x,nrm); a3.y=__fdiv_rn(a3.y,nrm); a3.z=__fdiv_rn(a3.z,nrm); a3.w=__fdiv_rn(a3.w,nrm);

    float s2 = 0.0f;
    s2 = fmaf(a0.x,a0.x,s2); s2 = fmaf(a0.y,a0.y,s2); s2 = fmaf(a0.z,a0.z,s2); s2 = fmaf(a0.w,a0.w,s2);
    s2 = fmaf(a1.x,a1.x,s2); s2 = fmaf(a1.y,a1.y,s2); s2 = fmaf(a1.z,a1.z,s2); s2 = fmaf(a1.w,a1.w,s2);
    s2 = fmaf(a2.x,a2.x,s2); s2 = fmaf(a2.y,a2.y,s2); s2 = fmaf(a2.z,a2.z,s2); s2 = fmaf(a2.w,a2.w,s2);
    s2 = fmaf(a3.x,a3.x,s2); s2 = fmaf(a3.y,a3.y,s2); s2 = fmaf(a3.z,a3.z,s2); s2 = fmaf(a3.w,a3.w,s2);
    #pragma unroll
    for (int off = 16; off > 0; off >>= 1)
        s2 = __fadd_rn(s2, __shfl_xor_sync(0xffffffffu, s2, off));

    float4* o = reinterpret_cast<float4*>(g_xn + (size_t)vec * DD);
    o[lane] = a0; o[lane + 32] = a1; o[lane + 64] = a2; o[lane + 96] = a3;
    if (lane == 0) g_sq[vec] = s2;
}

// ---------- Kernel 2: symmetric GEMM + dist + in-block partial top-K ----------
__global__ void __launch_bounds__(NTHR, 2)
MediumRangeEdge_11072425689094_kernel(const float* __restrict__ rel) {
    extern __shared__ char smraw[];
    float* sA0 = (float*)smraw;                    // [16][SA_ST]  7424 B
    float* sA1 = (float*)(smraw + 7424);
    ull*   sB0 = (ull*)(smraw + 14848);            // [16][SB_ST]  7424 B
    ull*   sB1 = (ull*)(smraw + 22272);
    float* sD  = (float*)smraw;                    // [112][SD_ST] 50624 B (aliases staging)

    const int b = blockIdx.x / NPAIR;
    int rem = blockIdx.x - b * NPAIR;
    int p = 0, cnt = NTB;
    while (rem >= cnt) { rem -= cnt; --cnt; ++p; }
    const int q = p + rem;
    const int pbase = p * BT, qbase = q * BT;

    const int tid = threadIdx.x;
    const int tx  = tid & 15;
    const int ty  = tid >> 4;

    const int r0 = tid >> 2,          kq0 = tid & 3;
    const int r1 = (tid + NTHR) >> 2, kq1 = (tid + NTHR) & 3;

    const float4* gA = (const float4*)(g_xn + ((size_t)b * NN + pbase) * DD);
    const float4* gB = (const float4*)(g_xn + ((size_t)b * NN + qbase) * DD);

    float4 fa0 = gA[r0 * (DD/4) + kq0], fa1 = gA[r1 * (DD/4) + kq1];
    float4 fb0 = gB[r0 * (DD/4) + kq0], fb1 = gB[r1 * (DD/4) + kq1];

    ull acc[7][4];
    #pragma unroll
    for (int s = 0; s < 7; ++s)
        #pragma unroll
        for (int c = 0; c < 4; ++c) acc[s][c] = 0ULL;

    for (int kc = 0; kc < DD / KC; ++kc) {
        float* A  = (kc & 1) ? sA1 : sA0;
        ull*   Bq = (kc & 1) ? sB1 : sB0;
        float* Bf = (float*)Bq;

        // STS A: k-major scatter
        A[(4*kq0+0)*SA_ST + r0] = fa0.x;
        A[(4*kq0+1)*SA_ST + r0] = fa0.y;
        A[(4*kq0+2)*SA_ST + r0] = fa0.z;
        A[(4*kq0+3)*SA_ST + r0] = fa0.w;
        A[(4*kq1+0)*SA_ST + r1] = fa1.x;
        A[(4*kq1+1)*SA_ST + r1] = fa1.y;
        A[(4*kq1+2)*SA_ST + r1] = fa1.z;
        A[(4*kq1+3)*SA_ST + r1] = fa1.w;
        // STS B: column-pair packed f32x2
        {
            const int c2 = r0 >> 1, h = r0 & 1;
            Bf[((4*kq0+0)*SB_ST + c2)*2 + h] = fb0.x;
            Bf[((4*kq0+1)*SB_ST + c2)*2 + h] = fb0.y;
            Bf[((4*kq0+2)*SB_ST + c2)*2 + h] = fb0.z;
            Bf[((4*kq0+3)*SB_ST + c2)*2 + h] = fb0.w;
        }
        {
            const int c2 = r1 >> 1, h = r1 & 1;
            Bf[((4*kq1+0)*SB_ST + c2)*2 + h] = fb1.x;
            Bf[((4*kq1+1)*SB_ST + c2)*2 + h] = fb1.y;
            Bf[((4*kq1+2)*SB_ST + c2)*2 + h] = fb1.z;
            Bf[((4*kq1+3)*SB_ST + c2)*2 + h] = fb1.w;
        }
        __syncthreads();

        if (kc + 1 < DD / KC) {
            const int ko = (kc + 1) * (KC / 4);
            fa0 = gA[r0*(DD/4) + ko + kq0]; fa1 = gA[r1*(DD/4) + ko + kq1];
            fb0 = gB[r0*(DD/4) + ko + kq0]; fb1 = gB[r1*(DD/4) + ko + kq1];
        }

        const float* Ar = A + tx;
        const ull*   Br = Bq + 4 * ty;
        #pragma unroll
        for (int kk = 0; kk < KC; ++kk) {
            const ulonglong2 bb0 = *(const ulonglong2*)(Br + kk*SB_ST);
            const ulonglong2 bb1 = *(const ulonglong2*)(Br + kk*SB_ST + 2);
            #pragma unroll
            for (int s = 0; s < 7; ++s) {
                const ull av = dup2(Ar[kk*SA_ST + 16*s]);
                acc[s][0] = fma2(av, bb0.x, acc[s][0]);
                acc[s][1] = fma2(av, bb0.y, acc[s][1]);
                acc[s][2] = fma2(av, bb1.x, acc[s][2]);
                acc[s][3] = fma2(av, bb1.y, acc[s][3]);
            }
        }
        __syncthreads();
    }

    // ---- epilogue: dist tile into sD ----
    float sqj[8]; int jr[8], jc[8];
    #pragma unroll
    for (int cc = 0; cc < 8; ++cc) {
        const int j = qbase + 8*ty + cc;
        sqj[cc] = g_sq[b*NN + j];
        jr[cc] = j / RESO; jc[cc] = j - jr[cc]*RESO;
    }
    #pragma unroll
    for (int s = 0; s < 7; ++s) {
        const int i  = pbase + tx + 16*s;
        const float sqi = g_sq[b*NN + i];
        const int ri = i / RESO, ci = i - ri*RESO;
        const float4 rl0 = *(const float4*)(rel + (size_t)i*NN + qbase + 8*ty);
        const float4 rl1 = *(const float4*)(rel + (size_t)i*NN + qbase + 8*ty + 4);
        const float rv[8] = {rl0.x, rl0.y, rl0.z, rl0.w, rl1.x, rl1.y, rl1.z, rl1.w};
        float* drow = sD + (tx + 16*s) * SD_ST + 8*ty;
        #pragma unroll
        for (int c = 0; c < 4; ++c) {
            const float d0 = lo2(acc[s][c]), d1 = hi2(acc[s][c]);
            float v0 = __fadd_rn(__fsub_rn(__fadd_rn(sqi, sqj[2*c]),
                                           __fmul_rn(2.0f, d0)), rv[2*c]);
            float v1 = __fadd_rn(__fsub_rn(__fadd_rn(sqi, sqj[2*c+1]),
                                           __fmul_rn(2.0f, d1)), rv[2*c+1]);
            int dr = ri - jr[2*c],   dc = ci - jc[2*c];
            if (dr >= -1 && dr <= 1 && dc >= -1 && dc <= 1) v0 = __fadd_rn(v0, INF_VAL);
            dr = ri - jr[2*c+1]; dc = ci - jc[2*c+1];
            if (dr >= -1 && dr <= 1 && dc >= -1 && dc <= 1) v1 = __fadd_rn(v1, INF_VAL);
            drow[2*c] = v0; drow[2*c+1] = v1;
        }
    }
    __syncthreads();

    // ---- in-block partial top-K: one thread per (row, side) ----
    ull list[KK];
    #pragma unroll
    for (int qq = 0; qq < KK; ++qq) list[qq] = ~0ULL;

    if (tid < BT) {
        // row side: row i = pbase + tid, candidates j = q-tile columns
        const float* rowp = sD + tid * SD_ST;
        #pragma unroll 4
        for (int c = 0; c < BT; ++c) {
            const ull key = ((ull)fmap(rowp[c]) << 32) | (unsigned)(qbase + c);
            if (key < list[KK-1]) {
                list[KK-1] = key;
                #pragma unroll
                for (int qq = KK-1; qq > 0; --qq)
                    if (list[qq] < list[qq-1]) {
                        const ull tk = list[qq-1]; list[qq-1] = list[qq]; list[qq] = tk;
                    }
            }
        }
        ull* dst = g_part + ((size_t)(b*NN + pbase + tid) * NTB + q) * KK;
        #pragma unroll
        for (int m = 0; m < KK/2; ++m)
            *(ulonglong2*)(dst + 2*m) = make_ulonglong2(list[2*m], list[2*m+1]);
    } else if (p != q) {
        // col side: row i = qbase + l, candidates j = p-tile rows (transposed read)
        const int l = tid - BT;
        #pragma unroll 4
        for (int r = 0; r < BT; ++r) {
            const ull key = ((ull)fmap(sD[r * SD_ST + l]) << 32) | (unsigned)(pbase + r);
            if (key < list[KK-1]) {
                list[KK-1] = key;
                #pragma unroll
                for (int qq = KK-1; qq > 0; --qq)
                    if (list[qq] < list[qq-1]) {
                        const ull tk = list[qq-1]; list[qq-1] = list[qq]; list[qq] = tk;
                    }
            }
        }
        ull* dst = g_part + ((size_t)(b*NN + qbase + l) * NTB + p) * KK;
        #pragma unroll
        for (int m = 0; m < KK/2; ++m)
            *(ulonglong2*)(dst + 2*m) = make_ulonglong2(list[2*m], list[2*m+1]);
    }
}

// ---------- Kernel 3: merge 7 partial lists per row -> edges ----------
__global__ void __launch_bounds__(256)
merge_kernel(float* __restrict__ out) {
    const int row  = blockIdx.x * 8 + (threadIdx.x >> 5);   // global row (b*N+i)
    const int lane = threadIdx.x & 31;
    const ull* part = g_part + (size_t)row * (NTB * KK);    // 70 keys

    ull a = part[lane];
    ull c2 = part[lane + 32];
    ull c3 = (lane < NTB*KK - 64) ? part[lane + 64] : ~0ULL;
    // sort3 ascending
    if (c2 < a)  { const ull t = a;  a  = c2; c2 = t; }
    if (c3 < c2) { const ull t = c2; c2 = c3; c3 = t; }
    if (c2 < a)  { const ull t = a;  a  = c2; c2 = t; }

    const int bofs = (row / NN) * NN;
    const int base = row * (KK * 3);
    #pragma unroll
    for (int k = 0; k < KK; ++k) {
        ull v = a;
        #pragma unroll
        for (int off = 16; off > 0; off >>= 1) {
            const ull o = __shfl_xor_sync(0xffffffffu, v, off);
            if (o < v) v = o;
        }
        if (lane == k) {
            out[base + 3*k + 0] = (float)((int)(v & 0xffffffffULL) + bofs);  // dst
            out[base + 3*k + 1] = (float)row;                                // src
            out[base + 3*k + 2] = 0.0f;                                      // relation
        }
        if (a == v) { a = c2; c2 = c3; c3 = ~0ULL; }   // keys unique: one popper
    }
}

extern "C" void kernel_launch(void* const* d_in, const int* in_sizes, int n_in,
                              void* d_out, int out_size) {
    (void)out_size;
    const float* node_feature = (const float*)d_in[0];
    const float* relative_pos = (const float*)d_in[1];
    if (n_in >= 2 && in_sizes[0] < in_sizes[1]) {
        node_feature = (const float*)d_in[1];
        relative_pos = (const float*)d_in[0];
    }
    float* out = (float*)d_out;

    const int smem = BT * SD_ST * (int)sizeof(float);   // 50624 B (covers staging)
    static int attr_done = 0;
    if (!attr_done) {
        cudaFuncSetAttribute(MediumRangeEdge_11072425689094_kernel,
                             cudaFuncAttributeMaxDynamicSharedMemorySize, smem);
        attr_done = 1;
    }

    norm_kernel<<<(BATCH * NN) / 8, 256>>>(node_feature);
    MediumRangeEdge_11072425689094_kernel<<<BATCH * NPAIR, NTHR, smem>>>(relative_pos);
    merge_kernel<<<(BATCH * NN) / 8, 256>>>(out);
}